// round 2
// baseline (speedup 1.0000x reference)
#include <cuda_runtime.h>

// Problem constants
#define Bv   64
#define Sv   512
#define Ev   1024
#define Hv   16
#define Dv   64
#define Mtot (Bv*Sv)   // 32768

// Scratch: __device__ globals (no allocs allowed anywhere)
__device__ float g_Q [Bv*Hv*Sv*Dv];   // [B,H,S,D]
__device__ float g_K [Bv*Hv*Sv*Dv];
__device__ float g_V [Bv*Hv*Sv*Dv];
__device__ float g_AO[Bv*Sv*Ev];      // attention out, [B,S,E]

// ---------------------------------------------------------------------------
// Tiled SGEMM core: C[128x128] tile, K-step 16, 256 threads, 8x8 microtile.
// As is stored transposed [k][m] with +4 pad to soften transpose-store conflicts.
// ---------------------------------------------------------------------------
#define BM  128
#define BN  128
#define BKs 16

__device__ __forceinline__ void gemm_tile(const float* __restrict__ A,
                                          const float* __restrict__ W,
                                          int row0, int col0,
                                          float acc[8][8],
                                          float (*As)[BM+4],
                                          float (*Bs)[BN])
{
    const int tid = threadIdx.x;
    const int tx  = tid & 15;
    const int ty  = tid >> 4;

    for (int k0 = 0; k0 < Ev; k0 += BKs) {
        // Load A tile (128x16) transposed, B tile (16x128) direct. 512 float4 each.
        #pragma unroll
        for (int i = 0; i < 2; i++) {
            int idx = tid + 256*i;
            int ar  = idx >> 2;
            int ac  = (idx & 3) << 2;
            float4 va = *(const float4*)&A[(size_t)(row0+ar)*Ev + k0 + ac];
            As[ac+0][ar] = va.x; As[ac+1][ar] = va.y;
            As[ac+2][ar] = va.z; As[ac+3][ar] = va.w;
            int br = idx >> 5;
            int bc = (idx & 31) << 2;
            *(float4*)&Bs[br][bc] = *(const float4*)&W[(size_t)(k0+br)*Ev + col0 + bc];
        }
        __syncthreads();

        #pragma unroll
        for (int kk = 0; kk < BKs; kk++) {
            float a[8], b[8];
            *(float4*)&a[0] = *(float4*)&As[kk][ty*8];
            *(float4*)&a[4] = *(float4*)&As[kk][ty*8 + 4];
            *(float4*)&b[0] = *(float4*)&Bs[kk][tx*8];
            *(float4*)&b[4] = *(float4*)&Bs[kk][tx*8 + 4];
            #pragma unroll
            for (int i = 0; i < 8; i++)
                #pragma unroll
                for (int j = 0; j < 8; j++)
                    acc[i][j] += a[i]*b[j];
        }
        __syncthreads();
    }
}

// ---------------------------------------------------------------------------
// QKV projection: X[32768,1024] @ {Wq,Wk,Wv}, scatter to [B,H,S,D].
// grid = (N/BN=8, M/BM=256, 3)
// ---------------------------------------------------------------------------
__global__ __launch_bounds__(256, 2)
void qkv_gemm(const float* __restrict__ X,
              const float* __restrict__ Wq,
              const float* __restrict__ Wk,
              const float* __restrict__ Wv)
{
    __shared__ float As[BKs][BM+4];
    __shared__ float Bs[BKs][BN];

    const float* W   = (blockIdx.z == 0) ? Wq : ((blockIdx.z == 1) ? Wk : Wv);
    float*       Out = (blockIdx.z == 0) ? g_Q : ((blockIdx.z == 1) ? g_K : g_V);

    const int row0 = blockIdx.y * BM;
    const int col0 = blockIdx.x * BN;

    float acc[8][8] = {};
    gemm_tile(X, W, row0, col0, acc, As, Bs);

    const int tx = threadIdx.x & 15;
    const int ty = threadIdx.x >> 4;
    #pragma unroll
    for (int i = 0; i < 8; i++) {
        int m  = row0 + ty*8 + i;
        int b  = m >> 9;          // / S
        int s  = m & 511;         // % S
        int n0 = col0 + tx*8;
        int h  = n0 >> 6;         // / D
        int d  = n0 & 63;         // % D  (8-aligned, stays within one head)
        float* dst = Out + ((size_t)(b*Hv + h)*Sv + s)*Dv + d;
        float4 v0 = make_float4(acc[i][0], acc[i][1], acc[i][2], acc[i][3]);
        float4 v1 = make_float4(acc[i][4], acc[i][5], acc[i][6], acc[i][7]);
        *(float4*)&dst[0] = v0;
        *(float4*)&dst[4] = v1;
    }
}

// ---------------------------------------------------------------------------
// Output projection: g_AO[32768,1024] @ Wo + bo -> d_out
// ---------------------------------------------------------------------------
__global__ __launch_bounds__(256, 2)
void out_gemm(const float* __restrict__ Wo,
              const float* __restrict__ bo,
              float* __restrict__ Cout)
{
    __shared__ float As[BKs][BM+4];
    __shared__ float Bs[BKs][BN];

    const int row0 = blockIdx.y * BM;
    const int col0 = blockIdx.x * BN;

    float acc[8][8] = {};
    gemm_tile(g_AO, Wo, row0, col0, acc, As, Bs);

    const int tx = threadIdx.x & 15;
    const int ty = threadIdx.x >> 4;
    const int n0 = col0 + tx*8;
    float4 bia0 = *(const float4*)&bo[n0];
    float4 bia1 = *(const float4*)&bo[n0 + 4];
    #pragma unroll
    for (int i = 0; i < 8; i++) {
        int m = row0 + ty*8 + i;
        float4 v0 = make_float4(acc[i][0]+bia0.x, acc[i][1]+bia0.y,
                                acc[i][2]+bia0.z, acc[i][3]+bia0.w);
        float4 v1 = make_float4(acc[i][4]+bia1.x, acc[i][5]+bia1.y,
                                acc[i][6]+bia1.z, acc[i][7]+bia1.w);
        *(float4*)&Cout[(size_t)m*Ev + n0]     = v0;
        *(float4*)&Cout[(size_t)m*Ev + n0 + 4] = v1;
    }
}

// ---------------------------------------------------------------------------
// Flash attention (fp32, causal, NO 1/sqrt(d) scale).
// Block: one (b, h, 64-query tile). 256 threads as 16(tx) x 16(ty).
// Thread owns 4 rows (ty*4+i) and 4 cols (tx*4+j) of each 64x64 tile.
// Row stats reduced over the 16 tx lanes via shfl.bfly {1,2,4,8}.
// Causal: key blocks beyond the query tile skipped; diagonal block masked.
// ---------------------------------------------------------------------------
__global__ __launch_bounds__(256)
void flash_attn()
{
    extern __shared__ float sm[];
    float (*Qs)[65] = (float(*)[65])(sm);
    float (*Ks)[65] = (float(*)[65])(sm + 64*65);
    float (*Ps)[65] = (float(*)[65])(sm + 2*64*65);
    float (*Vs)[64] = (float(*)[64])(sm + 3*64*65);

    const int qt = blockIdx.x;       // query tile 0..7
    const int h  = blockIdx.y;
    const int b  = blockIdx.z;
    const int q0 = qt * 64;

    const float* Qg = g_Q + (size_t)(b*Hv + h)*Sv*Dv;
    const float* Kg = g_K + (size_t)(b*Hv + h)*Sv*Dv;
    const float* Vg = g_V + (size_t)(b*Hv + h)*Sv*Dv;

    const int tid = threadIdx.x;
    const int tx  = tid & 15;
    const int ty  = tid >> 4;

    // Load Q tile
    for (int i = tid; i < 4096; i += 256) {
        int r = i >> 6, dd = i & 63;
        Qs[r][dd] = Qg[(size_t)(q0 + r)*Dv + dd];
    }

    float mst[4] = {-1e30f, -1e30f, -1e30f, -1e30f};
    float lst[4] = {0.f, 0.f, 0.f, 0.f};
    float O[4][4] = {};

    for (int kb = 0; kb <= qt; kb++) {
        const int k0 = kb * 64;
        __syncthreads();  // protect Ks/Vs/Ps reuse (also covers initial Qs load)

        for (int i = tid; i < 4096; i += 256) {
            int r = i >> 6, dd = i & 63;
            Ks[r][dd] = Kg[(size_t)(k0 + r)*Dv + dd];
        }
        for (int i = tid; i < 1024; i += 256) {
            int r = i >> 4, dd = (i & 15) << 2;
            *(float4*)&Vs[r][dd] = *(const float4*)&Vg[(size_t)(k0 + r)*Dv + dd];
        }
        __syncthreads();

        // S = Q K^T  (64x64 tile, dot over D=64)
        float s[4][4] = {};
        #pragma unroll 8
        for (int dd = 0; dd < 64; dd++) {
            float a[4], bb[4];
            #pragma unroll
            for (int i = 0; i < 4; i++) a[i]  = Qs[ty*4 + i][dd];
            #pragma unroll
            for (int j = 0; j < 4; j++) bb[j] = Ks[tx*4 + j][dd];
            #pragma unroll
            for (int i = 0; i < 4; i++)
                #pragma unroll
                for (int j = 0; j < 4; j++)
                    s[i][j] += a[i]*bb[j];
        }

        // Causal mask only on the diagonal block (k0 == q0 here)
        if (kb == qt) {
            #pragma unroll
            for (int i = 0; i < 4; i++)
                #pragma unroll
                for (int j = 0; j < 4; j++)
                    if (tx*4 + j > ty*4 + i) s[i][j] = -1e30f;
        }

        // Online softmax per row
        #pragma unroll
        for (int i = 0; i < 4; i++) {
            float mloc = fmaxf(fmaxf(s[i][0], s[i][1]), fmaxf(s[i][2], s[i][3]));
            #pragma unroll
            for (int msk = 1; msk < 16; msk <<= 1)
                mloc = fmaxf(mloc, __shfl_xor_sync(0xffffffffu, mloc, msk));
            float mnew  = fmaxf(mst[i], mloc);
            float alpha = __expf(mst[i] - mnew);
            float ps = 0.f;
            #pragma unroll
            for (int j = 0; j < 4; j++) {
                s[i][j] = __expf(s[i][j] - mnew);
                ps += s[i][j];
            }
            #pragma unroll
            for (int msk = 1; msk < 16; msk <<= 1)
                ps += __shfl_xor_sync(0xffffffffu, ps, msk);
            lst[i] = lst[i]*alpha + ps;
            mst[i] = mnew;
            #pragma unroll
            for (int j = 0; j < 4; j++) O[i][j] *= alpha;
            #pragma unroll
            for (int j = 0; j < 4; j++) Ps[tx*4 + j][ty*4 + i] = s[i][j];
        }
        __syncthreads();

        // O += P @ V
        #pragma unroll 8
        for (int k = 0; k < 64; k++) {
            float a[4];
            #pragma unroll
            for (int i = 0; i < 4; i++) a[i] = Ps[k][ty*4 + i];
            float4 bv = *(float4*)&Vs[k][tx*4];
            #pragma unroll
            for (int i = 0; i < 4; i++) {
                O[i][0] += a[i]*bv.x;
                O[i][1] += a[i]*bv.y;
                O[i][2] += a[i]*bv.z;
                O[i][3] += a[i]*bv.w;
            }
        }
    }

    // Normalize + write to [B,S,E] merged-head layout
    float* Og = g_AO + ((size_t)b*Sv + q0)*Ev + h*Dv;
    #pragma unroll
    for (int i = 0; i < 4; i++) {
        float inv = 1.f / lst[i];
        int r = ty*4 + i;
        float4 v = make_float4(O[i][0]*inv, O[i][1]*inv, O[i][2]*inv, O[i][3]*inv);
        *(float4*)&Og[(size_t)r*Ev + tx*4] = v;
    }
}

// ---------------------------------------------------------------------------
extern "C" void kernel_launch(void* const* d_in, const int* in_sizes, int n_in,
                              void* d_out, int out_size)
{
    const float* X  = (const float*)d_in[0];
    const float* Wq = (const float*)d_in[1];
    const float* Wk = (const float*)d_in[2];
    const float* Wv = (const float*)d_in[3];
    const float* Wo = (const float*)d_in[4];
    const float* bo = (const float*)d_in[5];
    float* out = (float*)d_out;

    const size_t flash_smem = (size_t)(3*64*65 + 64*64) * sizeof(float); // 66304 B
    cudaFuncSetAttribute(flash_attn, cudaFuncAttributeMaxDynamicSharedMemorySize,
                         (int)flash_smem);

    dim3 gq(Ev/BN, Mtot/BM, 3);              // (8, 256, 3)
    qkv_gemm<<<gq, 256>>>(X, Wq, Wk, Wv);

    flash_attn<<<dim3(Sv/64, Hv, Bv), 256, flash_smem>>>();

    dim3 go(Ev/BN, Mtot/BM);                 // (8, 256)
    out_gemm<<<go, 256>>>(Wo, bo, out);
}

// round 11
// speedup vs baseline: 1.8983x; 1.8983x over previous
#include <cuda_runtime.h>
#include <cuda_bf16.h>

// Problem constants
#define Bv   64
#define Sv   512
#define Ev   1024
#define Hv   16
#define Dv   64
#define Mtot (Bv*Sv)   // 32768

// ---------------------------------------------------------------------------
// Scratch (__device__ globals; no allocation allowed).
// NOTE: these symbols must ONLY be referenced from device code — passing them
// as kernel arguments from host code silently binds the host-side shadow
// (writable via GB300 ATS!) and leaves the device copy zero.
// ---------------------------------------------------------------------------
__device__ __nv_bfloat16 g_Xhi [Mtot*Ev];     // X split, [M,K] row-major
__device__ __nv_bfloat16 g_Xlo [Mtot*Ev];
__device__ __nv_bfloat16 g_Whi [4*Ev*Ev];     // W^T split, [N,K] per weight (q,k,v,o)
__device__ __nv_bfloat16 g_Wlo [4*Ev*Ev];
__device__ float         g_Q   [Mtot*Ev];     // [B,H,S,D]
__device__ float         g_K   [Mtot*Ev];
__device__ float         g_V   [Mtot*Ev];
__device__ __nv_bfloat16 g_AOhi[Mtot*Ev];     // attention out split, [B,S,E]
__device__ __nv_bfloat16 g_AOlo[Mtot*Ev];

// ---------------------------------------------------------------------------
// PTX helpers (Ampere-era: legal on plain sm_103 target)
// ---------------------------------------------------------------------------
__device__ __forceinline__ unsigned smem_u32(const void* p) {
    unsigned a;
    asm("{ .reg .u64 t; cvta.to.shared.u64 t, %1; cvt.u32.u64 %0, t; }" : "=r"(a) : "l"(p));
    return a;
}
__device__ __forceinline__ void cp_async16(unsigned s, const void* g) {
    asm volatile("cp.async.cg.shared.global [%0], [%1], 16;" :: "r"(s), "l"(g));
}
#define CP_COMMIT() asm volatile("cp.async.commit_group;" ::: "memory")
#define CP_WAIT(n)  asm volatile("cp.async.wait_group %0;" :: "n"(n) : "memory")

#define MMA_BF16(c, a, b) \
    asm volatile("mma.sync.aligned.m16n8k16.row.col.f32.bf16.bf16.f32 " \
        "{%0,%1,%2,%3}, {%4,%5,%6,%7}, {%8,%9}, {%0,%1,%2,%3};" \
        : "+f"((c)[0]), "+f"((c)[1]), "+f"((c)[2]), "+f"((c)[3]) \
        : "r"((a)[0]), "r"((a)[1]), "r"((a)[2]), "r"((a)[3]), \
          "r"((b)[0]), "r"((b)[1]))

// ---------------------------------------------------------------------------
// Split / transpose precompute kernels (write device globals directly!)
// ---------------------------------------------------------------------------
__global__ __launch_bounds__(256)
void split_x(const float* __restrict__ in, int n)
{
    for (long long i = ((long long)blockIdx.x * 256 + threadIdx.x) * 4; i < n;
         i += (long long)gridDim.x * 1024) {
        float4 v = *(const float4*)(in + i);
        __nv_bfloat16 h0 = __float2bfloat16(v.x), h1 = __float2bfloat16(v.y);
        __nv_bfloat16 h2 = __float2bfloat16(v.z), h3 = __float2bfloat16(v.w);
        __nv_bfloat16 l0 = __float2bfloat16(v.x - __bfloat162float(h0));
        __nv_bfloat16 l1 = __float2bfloat16(v.y - __bfloat162float(h1));
        __nv_bfloat16 l2 = __float2bfloat16(v.z - __bfloat162float(h2));
        __nv_bfloat16 l3 = __float2bfloat16(v.w - __bfloat162float(h3));
        *(__nv_bfloat162*)(g_Xhi + i)     = __nv_bfloat162(h0, h1);
        *(__nv_bfloat162*)(g_Xhi + i + 2) = __nv_bfloat162(h2, h3);
        *(__nv_bfloat162*)(g_Xlo + i)     = __nv_bfloat162(l0, l1);
        *(__nv_bfloat162*)(g_Xlo + i + 2) = __nv_bfloat162(l2, l3);
    }
}

// W [K,N] fp32 -> W^T [N,K] bf16 hi/lo. grid (32,32,4), block 256 (32x8)
__global__ __launch_bounds__(256)
void split_w(const float* __restrict__ Wq, const float* __restrict__ Wk,
             const float* __restrict__ Wv, const float* __restrict__ Wo)
{
    __shared__ float t[32][33];
    const float* W = (blockIdx.z == 0) ? Wq : (blockIdx.z == 1) ? Wk
                     : (blockIdx.z == 2) ? Wv : Wo;
    const int n0 = blockIdx.x * 32, k0 = blockIdx.y * 32;
    const int tx = threadIdx.x & 31, ty = threadIdx.x >> 5;
    #pragma unroll
    for (int i = 0; i < 4; i++)
        t[ty + i*8][tx] = W[(size_t)(k0 + ty + i*8) * Ev + n0 + tx];
    __syncthreads();
    const size_t zo = (size_t)blockIdx.z * Ev * Ev;
    #pragma unroll
    for (int i = 0; i < 4; i++) {
        float x = t[tx][ty + i*8];
        __nv_bfloat16 h = __float2bfloat16(x);
        __nv_bfloat16 l = __float2bfloat16(x - __bfloat162float(h));
        size_t o = zo + (size_t)(n0 + ty + i*8) * Ev + k0 + tx;
        g_Whi[o] = h;
        g_Wlo[o] = l;
    }
}

// ---------------------------------------------------------------------------
// HMMA (mma.sync bf16) GEMM mainloop, NO ldmatrix / NO swizzle.
// CTA tile 128x128, BK=32, 8 warps as (wm 0..1)x(wn 0..3) -> warp tile 64x32.
// Smem rows: 32 bf16 data padded to 40 bf16 (80 B = 20 words). Fragment LDS
// addresses derived directly from the PTX mma fragment tables:
//   A a0=(r,2t) a1=(r+8,2t) a2=(r,2t+8) a3=(r+8,2t+8); B b0=(2t,n) b1=(2t+8,n)
// with r=lane>>2, t=lane&3. Row stride 20 words -> 20*r mod 32 =
// {0,20,8,28,16,4,24,12}: all 32 lanes hit distinct banks (conflict-free).
// 3-term split: C = Ahi*Bhi + Ahi*Blo + Alo*Bhi  (fp32 accumulate).
// ---------------------------------------------------------------------------
#define KITERS 32         // 1024 / 32
#define TILEB  10240      // 128 rows * 80 bytes
#define BUFSZ  40960      // 4 tiles (Ahi, Alo, Bhi, Blo)
#define ROWW   20         // words per smem row

__device__ __forceinline__ void hmma_gemm_tile(
    const __nv_bfloat16* __restrict__ Ah, const __nv_bfloat16* __restrict__ Al,
    const __nv_bfloat16* __restrict__ Bh, const __nv_bfloat16* __restrict__ Bl,
    char* smp, unsigned sbase, float acc[4][4][4])
{
    const int tid  = threadIdx.x;
    const int lane = tid & 31;
    const int wid  = tid >> 5;
    const int wm   = (wid & 1) * 64;
    const int wn   = (wid >> 1) * 32;
    const int fr   = lane >> 2;     // 0..7
    const int ft   = lane & 3;      // 0..3

    // fill one buffer: 4 tiles x (128 rows x 4 chunks of 16B), 8 cp.async/thread
    auto fill = [&](int buf, int k0) {
        const unsigned boff = sbase + buf * BUFSZ;
        #pragma unroll
        for (int it = 0; it < 8; ++it) {
            const int t = it >> 1;                 // tile id (compile-time)
            int e = tid + (it & 1) * 256;          // 0..511
            int r = e >> 2, c = e & 3;
            const __nv_bfloat16* gb = (t == 0) ? Ah : (t == 1) ? Al
                                     : (t == 2) ? Bh : Bl;
            cp_async16(boff + t * TILEB + r * 80 + c * 16,
                       gb + (size_t)r * Ev + k0 + c * 8);
        }
    };

    fill(0, 0); CP_COMMIT();

    for (int cIt = 0; cIt < KITERS; ++cIt) {
        const int buf = cIt & 1;
        if (cIt + 1 < KITERS) { fill(buf ^ 1, (cIt + 1) * 32); CP_COMMIT(); CP_WAIT(1); }
        else                  { CP_WAIT(0); }
        __syncthreads();

        const unsigned* A_h = (const unsigned*)(smp + buf * BUFSZ);
        const unsigned* A_l = (const unsigned*)(smp + buf * BUFSZ + TILEB);
        const unsigned* B_h = (const unsigned*)(smp + buf * BUFSZ + 2 * TILEB);
        const unsigned* B_l = (const unsigned*)(smp + buf * BUFSZ + 3 * TILEB);

        #pragma unroll
        for (int ks2 = 0; ks2 < 16; ks2 += 8) {     // word offset of k-step (ks/2)
            unsigned bh[4][2], bl[4][2];
            #pragma unroll
            for (int na = 0; na < 4; ++na) {
                int base = (wn + na * 8 + fr) * ROWW + ks2 + ft;
                bh[na][0] = B_h[base];  bh[na][1] = B_h[base + 4];
                bl[na][0] = B_l[base];  bl[na][1] = B_l[base + 4];
            }
            #pragma unroll
            for (int ma = 0; ma < 4; ++ma) {
                int ab = (wm + ma * 16 + fr) * ROWW + ks2 + ft;
                unsigned ah[4], al[4];
                ah[0] = A_h[ab];            ah[1] = A_h[ab + 8 * ROWW];
                ah[2] = A_h[ab + 4];        ah[3] = A_h[ab + 8 * ROWW + 4];
                al[0] = A_l[ab];            al[1] = A_l[ab + 8 * ROWW];
                al[2] = A_l[ab + 4];        al[3] = A_l[ab + 8 * ROWW + 4];
                #pragma unroll
                for (int na = 0; na < 4; ++na) {
                    MMA_BF16(acc[ma][na], ah, bh[na]);
                    MMA_BF16(acc[ma][na], ah, bl[na]);
                    MMA_BF16(acc[ma][na], al, bh[na]);
                }
            }
        }
        __syncthreads();
    }
}

// ---------------------------------------------------------------------------
// QKV: X @ {Wq,Wk,Wv}, epilogue scatters to [B,H,S,D].  grid (8, 256, 3)
// ---------------------------------------------------------------------------
__global__ __launch_bounds__(256)
void qkv_mma()
{
    extern __shared__ char dsm[];
    unsigned raw   = smem_u32(dsm);
    unsigned sbase = (raw + 127) & ~127u;
    char* smp = dsm + (sbase - raw);

    const int z    = blockIdx.z;
    const int row0 = blockIdx.y * 128;
    const int col0 = blockIdx.x * 128;
    const size_t wz = (size_t)z * Ev * Ev;

    float acc[4][4][4] = {};
    hmma_gemm_tile(g_Xhi + (size_t)row0 * Ev, g_Xlo + (size_t)row0 * Ev,
                   g_Whi + wz + (size_t)col0 * Ev, g_Wlo + wz + (size_t)col0 * Ev,
                   smp, sbase, acc);

    float* Out = (z == 0) ? g_Q : (z == 1) ? g_K : g_V;
    const int lane = threadIdx.x & 31, wid = threadIdx.x >> 5;
    const int wm = (wid & 1) * 64, wn = (wid >> 1) * 32;
    const int grp = lane >> 2, tig = lane & 3;

    #pragma unroll
    for (int ma = 0; ma < 4; ++ma) {
        #pragma unroll
        for (int na = 0; na < 4; ++na) {
            int n = col0 + wn + na * 8 + tig * 2;
            int h = n >> 6, d = n & 63;
            #pragma unroll
            for (int half = 0; half < 2; ++half) {
                int m = row0 + wm + ma * 16 + grp + half * 8;
                int b = m >> 9, s = m & 511;
                float* dst = Out + ((size_t)(b * Hv + h) * Sv + s) * Dv + d;
                *(float2*)dst = make_float2(acc[ma][na][half*2], acc[ma][na][half*2+1]);
            }
        }
    }
}

// ---------------------------------------------------------------------------
// Output projection: AO @ Wo + bo -> out.  grid (8, 256)
// ---------------------------------------------------------------------------
__global__ __launch_bounds__(256)
void out_mma(const float* __restrict__ bo, float* __restrict__ Cout)
{
    extern __shared__ char dsm[];
    unsigned raw   = smem_u32(dsm);
    unsigned sbase = (raw + 127) & ~127u;
    char* smp = dsm + (sbase - raw);

    const int row0 = blockIdx.y * 128;
    const int col0 = blockIdx.x * 128;
    const size_t wz = (size_t)3 * Ev * Ev;

    float acc[4][4][4] = {};
    hmma_gemm_tile(g_AOhi + (size_t)row0 * Ev, g_AOlo + (size_t)row0 * Ev,
                   g_Whi + wz + (size_t)col0 * Ev, g_Wlo + wz + (size_t)col0 * Ev,
                   smp, sbase, acc);

    const int lane = threadIdx.x & 31, wid = threadIdx.x >> 5;
    const int wm = (wid & 1) * 64, wn = (wid >> 1) * 32;
    const int grp = lane >> 2, tig = lane & 3;

    #pragma unroll
    for (int ma = 0; ma < 4; ++ma) {
        #pragma unroll
        for (int na = 0; na < 4; ++na) {
            int n = col0 + wn + na * 8 + tig * 2;
            float2 bia = *(const float2*)(bo + n);
            #pragma unroll
            for (int half = 0; half < 2; ++half) {
                int m = row0 + wm + ma * 16 + grp + half * 8;
                float* dst = Cout + (size_t)m * Ev + n;
                *(float2*)dst = make_float2(acc[ma][na][half*2]   + bia.x,
                                            acc[ma][na][half*2+1] + bia.y);
            }
        }
    }
}

// ---------------------------------------------------------------------------
// Flash attention (fp32, causal, NO 1/sqrt(d) scale).
// Epilogue writes the hi/lo bf16 split of AO directly.
// ---------------------------------------------------------------------------
__global__ __launch_bounds__(256)
void flash_attn()
{
    extern __shared__ float sm[];
    float (*Qs)[65] = (float(*)[65])(sm);
    float (*Ks)[65] = (float(*)[65])(sm + 64*65);
    float (*Ps)[65] = (float(*)[65])(sm + 2*64*65);
    float (*Vs)[64] = (float(*)[64])(sm + 3*64*65);

    const int qt = blockIdx.x;
    const int h  = blockIdx.y;
    const int b  = blockIdx.z;
    const int q0 = qt * 64;

    const float* Qg = g_Q + (size_t)(b*Hv + h)*Sv*Dv;
    const float* Kg = g_K + (size_t)(b*Hv + h)*Sv*Dv;
    const float* Vg = g_V + (size_t)(b*Hv + h)*Sv*Dv;

    const int tid = threadIdx.x;
    const int tx  = tid & 15;
    const int ty  = tid >> 4;

    for (int i = tid; i < 4096; i += 256) {
        int r = i >> 6, dd = i & 63;
        Qs[r][dd] = Qg[(size_t)(q0 + r)*Dv + dd];
    }

    float mst[4] = {-1e30f, -1e30f, -1e30f, -1e30f};
    float lst[4] = {0.f, 0.f, 0.f, 0.f};
    float O[4][4] = {};

    for (int kb = 0; kb <= qt; kb++) {
        const int k0 = kb * 64;
        __syncthreads();

        for (int i = tid; i < 4096; i += 256) {
            int r = i >> 6, dd = i & 63;
            Ks[r][dd] = Kg[(size_t)(k0 + r)*Dv + dd];
        }
        for (int i = tid; i < 1024; i += 256) {
            int r = i >> 4, dd = (i & 15) << 2;
            *(float4*)&Vs[r][dd] = *(const float4*)&Vg[(size_t)(k0 + r)*Dv + dd];
        }
        __syncthreads();

        float s[4][4] = {};
        #pragma unroll 8
        for (int dd = 0; dd < 64; dd++) {
            float a[4], bb[4];
            #pragma unroll
            for (int i = 0; i < 4; i++) a[i]  = Qs[ty*4 + i][dd];
            #pragma unroll
            for (int j = 0; j < 4; j++) bb[j] = Ks[tx*4 + j][dd];
            #pragma unroll
            for (int i = 0; i < 4; i++)
                #pragma unroll
                for (int j = 0; j < 4; j++)
                    s[i][j] += a[i]*bb[j];
        }

        if (kb == qt) {
            #pragma unroll
            for (int i = 0; i < 4; i++)
                #pragma unroll
                for (int j = 0; j < 4; j++)
                    if (tx*4 + j > ty*4 + i) s[i][j] = -1e30f;
        }

        #pragma unroll
        for (int i = 0; i < 4; i++) {
            float mloc = fmaxf(fmaxf(s[i][0], s[i][1]), fmaxf(s[i][2], s[i][3]));
            #pragma unroll
            for (int msk = 1; msk < 16; msk <<= 1)
                mloc = fmaxf(mloc, __shfl_xor_sync(0xffffffffu, mloc, msk));
            float mnew  = fmaxf(mst[i], mloc);
            float alpha = __expf(mst[i] - mnew);
            float ps = 0.f;
            #pragma unroll
            for (int j = 0; j < 4; j++) {
                s[i][j] = __expf(s[i][j] - mnew);
                ps += s[i][j];
            }
            #pragma unroll
            for (int msk = 1; msk < 16; msk <<= 1)
                ps += __shfl_xor_sync(0xffffffffu, ps, msk);
            lst[i] = lst[i]*alpha + ps;
            mst[i] = mnew;
            #pragma unroll
            for (int j = 0; j < 4; j++) O[i][j] *= alpha;
            #pragma unroll
            for (int j = 0; j < 4; j++) Ps[tx*4 + j][ty*4 + i] = s[i][j];
        }
        __syncthreads();

        #pragma unroll 8
        for (int k = 0; k < 64; k++) {
            float a[4];
            #pragma unroll
            for (int i = 0; i < 4; i++) a[i] = Ps[k][ty*4 + i];
            float4 bv = *(float4*)&Vs[k][tx*4];
            #pragma unroll
            for (int i = 0; i < 4; i++) {
                O[i][0] += a[i]*bv.x;
                O[i][1] += a[i]*bv.y;
                O[i][2] += a[i]*bv.z;
                O[i][3] += a[i]*bv.w;
            }
        }
    }

    // Epilogue: normalize + write hi/lo bf16 split into [B,S,E] layout
    const size_t rowbase = ((size_t)b*Sv + q0) * Ev + h*Dv + tx*4;
    #pragma unroll
    for (int i = 0; i < 4; i++) {
        float inv = 1.f / lst[i];
        int r = ty*4 + i;
        size_t off = rowbase + (size_t)r * Ev;
        float v0 = O[i][0]*inv, v1 = O[i][1]*inv, v2 = O[i][2]*inv, v3 = O[i][3]*inv;
        __nv_bfloat16 h0 = __float2bfloat16(v0), h1 = __float2bfloat16(v1);
        __nv_bfloat16 h2 = __float2bfloat16(v2), h3 = __float2bfloat16(v3);
        __nv_bfloat16 l0 = __float2bfloat16(v0 - __bfloat162float(h0));
        __nv_bfloat16 l1 = __float2bfloat16(v1 - __bfloat162float(h1));
        __nv_bfloat16 l2 = __float2bfloat16(v2 - __bfloat162float(h2));
        __nv_bfloat16 l3 = __float2bfloat16(v3 - __bfloat162float(h3));
        *(__nv_bfloat162*)(g_AOhi + off)     = __nv_bfloat162(h0, h1);
        *(__nv_bfloat162*)(g_AOhi + off + 2) = __nv_bfloat162(h2, h3);
        *(__nv_bfloat162*)(g_AOlo + off)     = __nv_bfloat162(l0, l1);
        *(__nv_bfloat162*)(g_AOlo + off + 2) = __nv_bfloat162(l2, l3);
    }
}

// ---------------------------------------------------------------------------
extern "C" void kernel_launch(void* const* d_in, const int* in_sizes, int n_in,
                              void* d_out, int out_size)
{
    const float* X  = (const float*)d_in[0];
    const float* Wq = (const float*)d_in[1];
    const float* Wk = (const float*)d_in[2];
    const float* Wv = (const float*)d_in[3];
    const float* Wo = (const float*)d_in[4];
    const float* bo = (const float*)d_in[5];
    float* out = (float*)d_out;

    const int mma_smem = 2 * BUFSZ + 128;                        // 82048
    const size_t flash_smem = (size_t)(3*64*65 + 64*64) * sizeof(float);
    cudaFuncSetAttribute(qkv_mma, cudaFuncAttributeMaxDynamicSharedMemorySize, mma_smem);
    cudaFuncSetAttribute(out_mma, cudaFuncAttributeMaxDynamicSharedMemorySize, mma_smem);
    cudaFuncSetAttribute(flash_attn, cudaFuncAttributeMaxDynamicSharedMemorySize,
                         (int)flash_smem);

    split_x<<<4096, 256>>>(X, Mtot * Ev);
    split_w<<<dim3(32, 32, 4), 256>>>(Wq, Wk, Wv, Wo);

    qkv_mma<<<dim3(8, 256, 3), 256, mma_smem>>>();

    flash_attn<<<dim3(Sv/64, Hv, Bv), 256, flash_smem>>>();

    out_mma<<<dim3(8, 256), 256, mma_smem>>>(bo, out);
}

// round 13
// speedup vs baseline: 2.3170x; 1.2206x over previous
#include <cuda_runtime.h>
#include <cuda_bf16.h>

// Problem constants
#define Bv   64
#define Sv   512
#define Ev   1024
#define Hv   16
#define Dv   64
#define Mtot (Bv*Sv)   // 32768

// ---------------------------------------------------------------------------
// Scratch (__device__ globals; no allocation allowed).
// NOTE: reference these ONLY from device code (host-passed args bind the
// host-side shadow via GB300 ATS and silently corrupt).
// ---------------------------------------------------------------------------
__device__ __nv_bfloat16 g_Xhi [Mtot*Ev];     // X split, [M,K]
__device__ __nv_bfloat16 g_Xlo [Mtot*Ev];
__device__ __nv_bfloat16 g_Whi [4*Ev*Ev];     // W^T split, [N,K] per weight
__device__ __nv_bfloat16 g_Wlo [4*Ev*Ev];
__device__ __nv_bfloat16 g_Qhi [Mtot*Ev];     // [B,H,S,D] bf16 hi/lo
__device__ __nv_bfloat16 g_Qlo [Mtot*Ev];
__device__ __nv_bfloat16 g_Khi [Mtot*Ev];     // [B,H,S,D]
__device__ __nv_bfloat16 g_Klo [Mtot*Ev];
__device__ __nv_bfloat16 g_Vthi[Mtot*Ev];     // V transposed: [B,H,D,S]
__device__ __nv_bfloat16 g_Vtlo[Mtot*Ev];
__device__ __nv_bfloat16 g_AOhi[Mtot*Ev];     // attention out split, [B,S,E]
__device__ __nv_bfloat16 g_AOlo[Mtot*Ev];

// ---------------------------------------------------------------------------
// PTX helpers (Ampere-era: legal on plain sm_103 target)
// ---------------------------------------------------------------------------
__device__ __forceinline__ unsigned smem_u32(const void* p) {
    unsigned a;
    asm("{ .reg .u64 t; cvta.to.shared.u64 t, %1; cvt.u32.u64 %0, t; }" : "=r"(a) : "l"(p));
    return a;
}
__device__ __forceinline__ void cp_async16(unsigned s, const void* g) {
    asm volatile("cp.async.cg.shared.global [%0], [%1], 16;" :: "r"(s), "l"(g));
}
#define CP_COMMIT() asm volatile("cp.async.commit_group;" ::: "memory")
#define CP_WAIT(n)  asm volatile("cp.async.wait_group %0;" :: "n"(n) : "memory")

#define MMA_BF16(c, a, b) \
    asm volatile("mma.sync.aligned.m16n8k16.row.col.f32.bf16.bf16.f32 " \
        "{%0,%1,%2,%3}, {%4,%5,%6,%7}, {%8,%9}, {%0,%1,%2,%3};" \
        : "+f"((c)[0]), "+f"((c)[1]), "+f"((c)[2]), "+f"((c)[3]) \
        : "r"((a)[0]), "r"((a)[1]), "r"((a)[2]), "r"((a)[3]), \
          "r"((b)[0]), "r"((b)[1]))

// hi/lo bf16 split of a float pair, packed as bf16x2 words (low = first elem)
__device__ __forceinline__ void split2(float x0, float x1, unsigned& h, unsigned& l) {
    __nv_bfloat16 h0 = __float2bfloat16(x0), h1 = __float2bfloat16(x1);
    __nv_bfloat162 hh(h0, h1);
    __nv_bfloat162 ll(__float2bfloat16(x0 - __bfloat162float(h0)),
                      __float2bfloat16(x1 - __bfloat162float(h1)));
    h = *(unsigned*)&hh;
    l = *(unsigned*)&ll;
}

// ---------------------------------------------------------------------------
// Split / transpose precompute kernels (write device globals directly!)
// ---------------------------------------------------------------------------
__global__ __launch_bounds__(256)
void split_x(const float* __restrict__ in, int n)
{
    for (long long i = ((long long)blockIdx.x * 256 + threadIdx.x) * 4; i < n;
         i += (long long)gridDim.x * 1024) {
        float4 v = *(const float4*)(in + i);
        unsigned h0, l0, h1, l1;
        split2(v.x, v.y, h0, l0);
        split2(v.z, v.w, h1, l1);
        *(unsigned*)(g_Xhi + i)     = h0;
        *(unsigned*)(g_Xhi + i + 2) = h1;
        *(unsigned*)(g_Xlo + i)     = l0;
        *(unsigned*)(g_Xlo + i + 2) = l1;
    }
}

// W [K,N] fp32 -> W^T [N,K] bf16 hi/lo. grid (32,32,4), block 256 (32x8)
__global__ __launch_bounds__(256)
void split_w(const float* __restrict__ Wq, const float* __restrict__ Wk,
             const float* __restrict__ Wv, const float* __restrict__ Wo)
{
    __shared__ float t[32][33];
    const float* W = (blockIdx.z == 0) ? Wq : (blockIdx.z == 1) ? Wk
                     : (blockIdx.z == 2) ? Wv : Wo;
    const int n0 = blockIdx.x * 32, k0 = blockIdx.y * 32;
    const int tx = threadIdx.x & 31, ty = threadIdx.x >> 5;
    #pragma unroll
    for (int i = 0; i < 4; i++)
        t[ty + i*8][tx] = W[(size_t)(k0 + ty + i*8) * Ev + n0 + tx];
    __syncthreads();
    const size_t zo = (size_t)blockIdx.z * Ev * Ev;
    #pragma unroll
    for (int i = 0; i < 4; i++) {
        float x = t[tx][ty + i*8];
        __nv_bfloat16 h = __float2bfloat16(x);
        __nv_bfloat16 l = __float2bfloat16(x - __bfloat162float(h));
        size_t o = zo + (size_t)(n0 + ty + i*8) * Ev + k0 + tx;
        g_Whi[o] = h;
        g_Wlo[o] = l;
    }
}

// ---------------------------------------------------------------------------
// HMMA GEMM mainloop (unchanged from R11 — hardware-validated).
// ---------------------------------------------------------------------------
#define KITERS 32         // 1024 / 32
#define TILEB  10240      // 128 rows * 80 bytes
#define BUFSZ  40960      // 4 tiles (Ahi, Alo, Bhi, Blo)
#define ROWW   20         // words per smem row

__device__ __forceinline__ void hmma_gemm_tile(
    const __nv_bfloat16* __restrict__ Ah, const __nv_bfloat16* __restrict__ Al,
    const __nv_bfloat16* __restrict__ Bh, const __nv_bfloat16* __restrict__ Bl,
    char* smp, unsigned sbase, float acc[4][4][4])
{
    const int tid  = threadIdx.x;
    const int lane = tid & 31;
    const int wid  = tid >> 5;
    const int wm   = (wid & 1) * 64;
    const int wn   = (wid >> 1) * 32;
    const int fr   = lane >> 2;     // 0..7
    const int ft   = lane & 3;      // 0..3

    auto fill = [&](int buf, int k0) {
        const unsigned boff = sbase + buf * BUFSZ;
        #pragma unroll
        for (int it = 0; it < 8; ++it) {
            const int t = it >> 1;
            int e = tid + (it & 1) * 256;
            int r = e >> 2, c = e & 3;
            const __nv_bfloat16* gb = (t == 0) ? Ah : (t == 1) ? Al
                                     : (t == 2) ? Bh : Bl;
            cp_async16(boff + t * TILEB + r * 80 + c * 16,
                       gb + (size_t)r * Ev + k0 + c * 8);
        }
    };

    fill(0, 0); CP_COMMIT();

    for (int cIt = 0; cIt < KITERS; ++cIt) {
        const int buf = cIt & 1;
        if (cIt + 1 < KITERS) { fill(buf ^ 1, (cIt + 1) * 32); CP_COMMIT(); CP_WAIT(1); }
        else                  { CP_WAIT(0); }
        __syncthreads();

        const unsigned* A_h = (const unsigned*)(smp + buf * BUFSZ);
        const unsigned* A_l = (const unsigned*)(smp + buf * BUFSZ + TILEB);
        const unsigned* B_h = (const unsigned*)(smp + buf * BUFSZ + 2 * TILEB);
        const unsigned* B_l = (const unsigned*)(smp + buf * BUFSZ + 3 * TILEB);

        #pragma unroll
        for (int ks2 = 0; ks2 < 16; ks2 += 8) {
            unsigned bh[4][2], bl[4][2];
            #pragma unroll
            for (int na = 0; na < 4; ++na) {
                int base = (wn + na * 8 + fr) * ROWW + ks2 + ft;
                bh[na][0] = B_h[base];  bh[na][1] = B_h[base + 4];
                bl[na][0] = B_l[base];  bl[na][1] = B_l[base + 4];
            }
            #pragma unroll
            for (int ma = 0; ma < 4; ++ma) {
                int ab = (wm + ma * 16 + fr) * ROWW + ks2 + ft;
                unsigned ah[4], al[4];
                ah[0] = A_h[ab];            ah[1] = A_h[ab + 8 * ROWW];
                ah[2] = A_h[ab + 4];        ah[3] = A_h[ab + 8 * ROWW + 4];
                al[0] = A_l[ab];            al[1] = A_l[ab + 8 * ROWW];
                al[2] = A_l[ab + 4];        al[3] = A_l[ab + 8 * ROWW + 4];
                #pragma unroll
                for (int na = 0; na < 4; ++na) {
                    MMA_BF16(acc[ma][na], ah, bh[na]);
                    MMA_BF16(acc[ma][na], ah, bl[na]);
                    MMA_BF16(acc[ma][na], al, bh[na]);
                }
            }
        }
        __syncthreads();
    }
}

// ---------------------------------------------------------------------------
// QKV: X @ {Wq,Wk,Wv}. Epilogue writes bf16 hi/lo:
//   z=0 -> Q [B,H,S,D], z=1 -> K [B,H,S,D], z=2 -> V^T [B,H,D,S]
// grid (8, 256, 3)
// ---------------------------------------------------------------------------
__global__ __launch_bounds__(256)
void qkv_mma()
{
    extern __shared__ char dsm[];
    unsigned raw   = smem_u32(dsm);
    unsigned sbase = (raw + 127) & ~127u;
    char* smp = dsm + (sbase - raw);

    const int z    = blockIdx.z;
    const int row0 = blockIdx.y * 128;
    const int col0 = blockIdx.x * 128;
    const size_t wz = (size_t)z * Ev * Ev;

    float acc[4][4][4] = {};
    hmma_gemm_tile(g_Xhi + (size_t)row0 * Ev, g_Xlo + (size_t)row0 * Ev,
                   g_Whi + wz + (size_t)col0 * Ev, g_Wlo + wz + (size_t)col0 * Ev,
                   smp, sbase, acc);

    const int lane = threadIdx.x & 31, wid = threadIdx.x >> 5;
    const int wm = (wid & 1) * 64, wn = (wid >> 1) * 32;
    const int grp = lane >> 2, tig = lane & 3;

    if (z < 2) {
        __nv_bfloat16* Ohi = (z == 0) ? g_Qhi : g_Khi;
        __nv_bfloat16* Olo = (z == 0) ? g_Qlo : g_Klo;
        #pragma unroll
        for (int ma = 0; ma < 4; ++ma) {
            #pragma unroll
            for (int na = 0; na < 4; ++na) {
                int n = col0 + wn + na * 8 + tig * 2;
                int h = n >> 6, d = n & 63;
                #pragma unroll
                for (int half = 0; half < 2; ++half) {
                    int m = row0 + wm + ma * 16 + grp + half * 8;
                    int b = m >> 9, s = m & 511;
                    size_t off = ((size_t)(b * Hv + h) * Sv + s) * Dv + d;
                    unsigned hw, lw;
                    split2(acc[ma][na][half*2], acc[ma][na][half*2+1], hw, lw);
                    *(unsigned*)(Ohi + off) = hw;
                    *(unsigned*)(Olo + off) = lw;
                }
            }
        }
    } else {
        #pragma unroll
        for (int ma = 0; ma < 4; ++ma) {
            #pragma unroll
            for (int na = 0; na < 4; ++na) {
                int n = col0 + wn + na * 8 + tig * 2;
                int h = n >> 6, d = n & 63;
                #pragma unroll
                for (int half = 0; half < 2; ++half) {
                    int m = row0 + wm + ma * 16 + grp + half * 8;
                    int b = m >> 9, s = m & 511;
                    #pragma unroll
                    for (int e = 0; e < 2; ++e) {
                        float x = acc[ma][na][half*2 + e];
                        __nv_bfloat16 hh = __float2bfloat16(x);
                        __nv_bfloat16 ll = __float2bfloat16(x - __bfloat162float(hh));
                        size_t off = ((size_t)(b * Hv + h) * Dv + d + e) * Sv + s;
                        g_Vthi[off] = hh;
                        g_Vtlo[off] = ll;
                    }
                }
            }
        }
    }
}

// ---------------------------------------------------------------------------
// Output projection: AO @ Wo + bo -> out.  grid (8, 256)
// ---------------------------------------------------------------------------
__global__ __launch_bounds__(256)
void out_mma(const float* __restrict__ bo, float* __restrict__ Cout)
{
    extern __shared__ char dsm[];
    unsigned raw   = smem_u32(dsm);
    unsigned sbase = (raw + 127) & ~127u;
    char* smp = dsm + (sbase - raw);

    const int row0 = blockIdx.y * 128;
    const int col0 = blockIdx.x * 128;
    const size_t wz = (size_t)3 * Ev * Ev;

    float acc[4][4][4] = {};
    hmma_gemm_tile(g_AOhi + (size_t)row0 * Ev, g_AOlo + (size_t)row0 * Ev,
                   g_Whi + wz + (size_t)col0 * Ev, g_Wlo + wz + (size_t)col0 * Ev,
                   smp, sbase, acc);

    const int lane = threadIdx.x & 31, wid = threadIdx.x >> 5;
    const int wm = (wid & 1) * 64, wn = (wid >> 1) * 32;
    const int grp = lane >> 2, tig = lane & 3;

    #pragma unroll
    for (int ma = 0; ma < 4; ++ma) {
        #pragma unroll
        for (int na = 0; na < 4; ++na) {
            int n = col0 + wn + na * 8 + tig * 2;
            float2 bia = *(const float2*)(bo + n);
            #pragma unroll
            for (int half = 0; half < 2; ++half) {
                int m = row0 + wm + ma * 16 + grp + half * 8;
                float* dst = Cout + (size_t)m * Ev + n;
                *(float2*)dst = make_float2(acc[ma][na][half*2]   + bia.x,
                                            acc[ma][na][half*2+1] + bia.y);
            }
        }
    }
}

// ---------------------------------------------------------------------------
// Tensorized flash attention (causal, NO 1/sqrt(d) scale).
// Block: (b, h, 128-query tile). 8 warps x 16 rows. 64-key blocks,
// double-buffered cp.async (K hi/lo [key][d], V^T hi/lo [d][key]).
// 36-word padded smem rows -> conflict-free fragment LDS (proven pattern).
// S and P@V via 3-term bf16 mma.sync; softmax in registers (quad shfl).
// ---------------------------------------------------------------------------
#define TROW 36                 // words per smem row
#define TSZ  (64 * TROW * 4)    // 9216 B per tile
#define FBUF (4 * TSZ)          // 36864 B per buffer (Kh, Kl, Vth, Vtl)

__global__ __launch_bounds__(256)
void flash_attn()
{
    extern __shared__ char dsm[];
    unsigned raw   = smem_u32(dsm);
    unsigned sbase = (raw + 127) & ~127u;
    char* smp = dsm + (sbase - raw);

    const int qt = blockIdx.x;          // 0..3 (128-row q tiles)
    const int h  = blockIdx.y;
    const int b  = blockIdx.z;
    const int q0 = qt * 128;

    const int tid  = threadIdx.x;
    const int lane = tid & 31;
    const int wid  = tid >> 5;
    const int grp  = lane >> 2;         // 0..7
    const int ft   = lane & 3;          // 0..3
    const int wm   = wid * 16;

    const long long bh = (long long)b * Hv + h;

    // Q fragments (persistent in registers): rows q0+wm .. +15, 32 words/row
    const unsigned* Qhw = (const unsigned*)g_Qhi + (bh * Sv + q0 + wm) * 32;
    const unsigned* Qlw = (const unsigned*)g_Qlo + (bh * Sv + q0 + wm) * 32;
    unsigned qh[4][4], ql[4][4];
    #pragma unroll
    for (int kc = 0; kc < 4; ++kc) {
        int w0 = grp * 32 + kc * 8 + ft;
        qh[kc][0] = Qhw[w0];       qh[kc][1] = Qhw[w0 + 256];
        qh[kc][2] = Qhw[w0 + 4];   qh[kc][3] = Qhw[w0 + 260];
        ql[kc][0] = Qlw[w0];       ql[kc][1] = Qlw[w0 + 256];
        ql[kc][2] = Qlw[w0 + 4];   ql[kc][3] = Qlw[w0 + 260];
    }

    const __nv_bfloat16* Kh  = g_Khi  + bh * Sv * Dv;
    const __nv_bfloat16* Kl  = g_Klo  + bh * Sv * Dv;
    const __nv_bfloat16* Vth = g_Vthi + bh * Dv * Sv;
    const __nv_bfloat16* Vtl = g_Vtlo + bh * Dv * Sv;

    float O[8][4] = {};
    float m0 = -1e30f, m1 = -1e30f, l0 = 0.f, l1 = 0.f;

    const int kbmax = 2 * (qt + 1);

    auto fill = [&](int buf, int kb) {
        const unsigned boff = sbase + buf * FBUF;
        #pragma unroll
        for (int it = 0; it < 8; ++it) {
            const int t = it >> 1;
            int e = tid + (it & 1) * 256;     // 0..511
            int r = e >> 3, c = e & 7;
            const __nv_bfloat16* g;
            if      (t == 0) g = Kh  + (size_t)(kb * 64 + r) * Dv + c * 8;
            else if (t == 1) g = Kl  + (size_t)(kb * 64 + r) * Dv + c * 8;
            else if (t == 2) g = Vth + (size_t)r * Sv + kb * 64 + c * 8;
            else             g = Vtl + (size_t)r * Sv + kb * 64 + c * 8;
            cp_async16(boff + t * TSZ + r * 144 + c * 16, g);
        }
    };

    fill(0, 0); CP_COMMIT();

    for (int kb = 0; kb < kbmax; ++kb) {
        const int buf = kb & 1;
        if (kb + 1 < kbmax) { fill(buf ^ 1, kb + 1); CP_COMMIT(); CP_WAIT(1); }
        else                { CP_WAIT(0); }
        __syncthreads();

        const unsigned* SK_h = (const unsigned*)(smp + buf * FBUF);
        const unsigned* SK_l = (const unsigned*)(smp + buf * FBUF + TSZ);
        const unsigned* SV_h = (const unsigned*)(smp + buf * FBUF + 2 * TSZ);
        const unsigned* SV_l = (const unsigned*)(smp + buf * FBUF + 3 * TSZ);

        // S = Q @ K^T (16x64 per warp), 3-term split
        float sacc[8][4] = {};
        #pragma unroll
        for (int kc = 0; kc < 4; ++kc) {
            unsigned bhf[8][2], blf[8][2];
            #pragma unroll
            for (int nt = 0; nt < 8; ++nt) {
                int w = (nt * 8 + grp) * TROW + kc * 8 + ft;
                bhf[nt][0] = SK_h[w];  bhf[nt][1] = SK_h[w + 4];
                blf[nt][0] = SK_l[w];  blf[nt][1] = SK_l[w + 4];
            }
            #pragma unroll
            for (int nt = 0; nt < 8; ++nt) {
                MMA_BF16(sacc[nt], qh[kc], bhf[nt]);
                MMA_BF16(sacc[nt], qh[kc], blf[nt]);
                MMA_BF16(sacc[nt], ql[kc], bhf[nt]);
            }
        }

        // causal mask (only the last two key blocks can cross the diagonal)
        if (kb >= kbmax - 2) {
            int r0 = q0 + wm + grp, r1 = r0 + 8;
            #pragma unroll
            for (int nt = 0; nt < 8; ++nt) {
                int c0 = kb * 64 + nt * 8 + 2 * ft;
                if (c0     > r0) sacc[nt][0] = -1e30f;
                if (c0 + 1 > r0) sacc[nt][1] = -1e30f;
                if (c0     > r1) sacc[nt][2] = -1e30f;
                if (c0 + 1 > r1) sacc[nt][3] = -1e30f;
            }
        }

        // online softmax in registers (rows grp / grp+8; quad holds full row)
        float mx0 = -1e30f, mx1 = -1e30f;
        #pragma unroll
        for (int nt = 0; nt < 8; ++nt) {
            mx0 = fmaxf(mx0, fmaxf(sacc[nt][0], sacc[nt][1]));
            mx1 = fmaxf(mx1, fmaxf(sacc[nt][2], sacc[nt][3]));
        }
        mx0 = fmaxf(mx0, __shfl_xor_sync(0xffffffffu, mx0, 1));
        mx0 = fmaxf(mx0, __shfl_xor_sync(0xffffffffu, mx0, 2));
        mx1 = fmaxf(mx1, __shfl_xor_sync(0xffffffffu, mx1, 1));
        mx1 = fmaxf(mx1, __shfl_xor_sync(0xffffffffu, mx1, 2));

        float mn0 = fmaxf(m0, mx0), mn1 = fmaxf(m1, mx1);
        float al0 = __expf(m0 - mn0), al1 = __expf(m1 - mn1);
        float ps0 = 0.f, ps1 = 0.f;
        #pragma unroll
        for (int nt = 0; nt < 8; ++nt) {
            sacc[nt][0] = __expf(sacc[nt][0] - mn0);
            sacc[nt][1] = __expf(sacc[nt][1] - mn0);
            sacc[nt][2] = __expf(sacc[nt][2] - mn1);
            sacc[nt][3] = __expf(sacc[nt][3] - mn1);
            ps0 += sacc[nt][0] + sacc[nt][1];
            ps1 += sacc[nt][2] + sacc[nt][3];
        }
        ps0 += __shfl_xor_sync(0xffffffffu, ps0, 1);
        ps0 += __shfl_xor_sync(0xffffffffu, ps0, 2);
        ps1 += __shfl_xor_sync(0xffffffffu, ps1, 1);
        ps1 += __shfl_xor_sync(0xffffffffu, ps1, 2);
        l0 = l0 * al0 + ps0;  l1 = l1 * al1 + ps1;
        m0 = mn0;             m1 = mn1;
        #pragma unroll
        for (int nt = 0; nt < 8; ++nt) {
            O[nt][0] *= al0;  O[nt][1] *= al0;
            O[nt][2] *= al1;  O[nt][3] *= al1;
        }

        // repack P (C layout -> A fragments, hi/lo split), lane-local
        unsigned ph[4][4], pl[4][4];
        #pragma unroll
        for (int kc = 0; kc < 4; ++kc) {
            split2(sacc[2*kc][0],   sacc[2*kc][1],   ph[kc][0], pl[kc][0]);
            split2(sacc[2*kc][2],   sacc[2*kc][3],   ph[kc][1], pl[kc][1]);
            split2(sacc[2*kc+1][0], sacc[2*kc+1][1], ph[kc][2], pl[kc][2]);
            split2(sacc[2*kc+1][2], sacc[2*kc+1][3], ph[kc][3], pl[kc][3]);
        }

        // O += P @ V  (V^T tile in smem is exactly B-fragment layout)
        #pragma unroll
        for (int kc = 0; kc < 4; ++kc) {
            unsigned vh[8][2], vl[8][2];
            #pragma unroll
            for (int nt = 0; nt < 8; ++nt) {
                int w = (nt * 8 + grp) * TROW + kc * 8 + ft;
                vh[nt][0] = SV_h[w];  vh[nt][1] = SV_h[w + 4];
                vl[nt][0] = SV_l[w];  vl[nt][1] = SV_l[w + 4];
            }
            #pragma unroll
            for (int nt = 0; nt < 8; ++nt) {
                MMA_BF16(O[nt], ph[kc], vh[nt]);
                MMA_BF16(O[nt], ph[kc], vl[nt]);
                MMA_BF16(O[nt], pl[kc], vh[nt]);
            }
        }
        __syncthreads();
    }

    // normalize + write AO hi/lo split into [B,S,E]
    float inv0 = 1.f / l0, inv1 = 1.f / l1;
    int r0 = q0 + wm + grp, r1 = r0 + 8;
    #pragma unroll
    for (int nt = 0; nt < 8; ++nt) {
        int d = nt * 8 + 2 * ft;
        size_t off0 = ((size_t)b * Sv + r0) * Ev + h * 64 + d;
        size_t off1 = ((size_t)b * Sv + r1) * Ev + h * 64 + d;
        unsigned hw, lw;
        split2(O[nt][0] * inv0, O[nt][1] * inv0, hw, lw);
        *(unsigned*)(g_AOhi + off0) = hw;
        *(unsigned*)(g_AOlo + off0) = lw;
        split2(O[nt][2] * inv1, O[nt][3] * inv1, hw, lw);
        *(unsigned*)(g_AOhi + off1) = hw;
        *(unsigned*)(g_AOlo + off1) = lw;
    }
}

// ---------------------------------------------------------------------------
extern "C" void kernel_launch(void* const* d_in, const int* in_sizes, int n_in,
                              void* d_out, int out_size)
{
    const float* X  = (const float*)d_in[0];
    const float* Wq = (const float*)d_in[1];
    const float* Wk = (const float*)d_in[2];
    const float* Wv = (const float*)d_in[3];
    const float* Wo = (const float*)d_in[4];
    const float* bo = (const float*)d_in[5];
    float* out = (float*)d_out;

    const int mma_smem   = 2 * BUFSZ + 128;       // 82048
    const int flash_smem = 2 * FBUF + 128;        // 73856
    cudaFuncSetAttribute(qkv_mma, cudaFuncAttributeMaxDynamicSharedMemorySize, mma_smem);
    cudaFuncSetAttribute(out_mma, cudaFuncAttributeMaxDynamicSharedMemorySize, mma_smem);
    cudaFuncSetAttribute(flash_attn, cudaFuncAttributeMaxDynamicSharedMemorySize, flash_smem);

    split_x<<<4096, 256>>>(X, Mtot * Ev);
    split_w<<<dim3(32, 32, 4), 256>>>(Wq, Wk, Wv, Wo);

    qkv_mma<<<dim3(8, 256, 3), 256, mma_smem>>>();

    flash_attn<<<dim3(4, Hv, Bv), 256, flash_smem>>>();

    out_mma<<<dim3(8, 256), 256, mma_smem>>>(bo, out);
}

// round 14
// speedup vs baseline: 2.3962x; 1.0342x over previous
#include <cuda_runtime.h>
#include <cuda_bf16.h>

// Problem constants
#define Bv   64
#define Sv   512
#define Ev   1024
#define Hv   16
#define Dv   64
#define Mtot (Bv*Sv)   // 32768

// ---------------------------------------------------------------------------
// Scratch (__device__ globals; no allocation allowed).
// NOTE: reference these ONLY from device code (host-passed args bind the
// host-side shadow via GB300 ATS and silently corrupt).
// ---------------------------------------------------------------------------
__device__ __nv_bfloat16 g_Xhi [Mtot*Ev];     // X split, [M,K]
__device__ __nv_bfloat16 g_Xlo [Mtot*Ev];
__device__ __nv_bfloat16 g_Whi [4*Ev*Ev];     // W^T split, [N,K] per weight
__device__ __nv_bfloat16 g_Wlo [4*Ev*Ev];
__device__ __nv_bfloat16 g_Qhi [Mtot*Ev];     // [B,H,S,D] bf16 hi/lo
__device__ __nv_bfloat16 g_Qlo [Mtot*Ev];
__device__ __nv_bfloat16 g_Khi [Mtot*Ev];     // [B,H,S,D]
__device__ __nv_bfloat16 g_Klo [Mtot*Ev];
__device__ __nv_bfloat16 g_Vthi[Mtot*Ev];     // V transposed: [B,H,D,S]
__device__ __nv_bfloat16 g_Vtlo[Mtot*Ev];
__device__ __nv_bfloat16 g_AOhi[Mtot*Ev];     // attention out split, [B,S,E]
__device__ __nv_bfloat16 g_AOlo[Mtot*Ev];

// ---------------------------------------------------------------------------
// PTX helpers (Ampere-era: legal on plain sm_103 target)
// ---------------------------------------------------------------------------
__device__ __forceinline__ unsigned smem_u32(const void* p) {
    unsigned a;
    asm("{ .reg .u64 t; cvta.to.shared.u64 t, %1; cvt.u32.u64 %0, t; }" : "=r"(a) : "l"(p));
    return a;
}
__device__ __forceinline__ void cp_async16(unsigned s, const void* g) {
    asm volatile("cp.async.cg.shared.global [%0], [%1], 16;" :: "r"(s), "l"(g));
}
#define CP_COMMIT() asm volatile("cp.async.commit_group;" ::: "memory")
#define CP_WAIT(n)  asm volatile("cp.async.wait_group %0;" :: "n"(n) : "memory")

#define MMA_BF16(c, a, b) \
    asm volatile("mma.sync.aligned.m16n8k16.row.col.f32.bf16.bf16.f32 " \
        "{%0,%1,%2,%3}, {%4,%5,%6,%7}, {%8,%9}, {%0,%1,%2,%3};" \
        : "+f"((c)[0]), "+f"((c)[1]), "+f"((c)[2]), "+f"((c)[3]) \
        : "r"((a)[0]), "r"((a)[1]), "r"((a)[2]), "r"((a)[3]), \
          "r"((b)[0]), "r"((b)[1]))

// hi/lo bf16 split of a float pair, packed as bf16x2 words (low = first elem)
__device__ __forceinline__ void split2(float x0, float x1, unsigned& h, unsigned& l) {
    __nv_bfloat16 h0 = __float2bfloat16(x0), h1 = __float2bfloat16(x1);
    __nv_bfloat162 hh(h0, h1);
    __nv_bfloat162 ll(__float2bfloat16(x0 - __bfloat162float(h0)),
                      __float2bfloat16(x1 - __bfloat162float(h1)));
    h = *(unsigned*)&hh;
    l = *(unsigned*)&ll;
}

// ---------------------------------------------------------------------------
// Split / transpose precompute kernels (write device globals directly!)
// ---------------------------------------------------------------------------
__global__ __launch_bounds__(256)
void split_x(const float* __restrict__ in, int n)
{
    for (long long i = ((long long)blockIdx.x * 256 + threadIdx.x) * 4; i < n;
         i += (long long)gridDim.x * 1024) {
        float4 v = *(const float4*)(in + i);
        unsigned h0, l0, h1, l1;
        split2(v.x, v.y, h0, l0);
        split2(v.z, v.w, h1, l1);
        *(unsigned*)(g_Xhi + i)     = h0;
        *(unsigned*)(g_Xhi + i + 2) = h1;
        *(unsigned*)(g_Xlo + i)     = l0;
        *(unsigned*)(g_Xlo + i + 2) = l1;
    }
}

// W [K,N] fp32 -> W^T [N,K] bf16 hi/lo. grid (32,32,4), block 256 (32x8)
__global__ __launch_bounds__(256)
void split_w(const float* __restrict__ Wq, const float* __restrict__ Wk,
             const float* __restrict__ Wv, const float* __restrict__ Wo)
{
    __shared__ float t[32][33];
    const float* W = (blockIdx.z == 0) ? Wq : (blockIdx.z == 1) ? Wk
                     : (blockIdx.z == 2) ? Wv : Wo;
    const int n0 = blockIdx.x * 32, k0 = blockIdx.y * 32;
    const int tx = threadIdx.x & 31, ty = threadIdx.x >> 5;
    #pragma unroll
    for (int i = 0; i < 4; i++)
        t[ty + i*8][tx] = W[(size_t)(k0 + ty + i*8) * Ev + n0 + tx];
    __syncthreads();
    const size_t zo = (size_t)blockIdx.z * Ev * Ev;
    #pragma unroll
    for (int i = 0; i < 4; i++) {
        float x = t[tx][ty + i*8];
        __nv_bfloat16 h = __float2bfloat16(x);
        __nv_bfloat16 l = __float2bfloat16(x - __bfloat162float(h));
        size_t o = zo + (size_t)(n0 + ty + i*8) * Ev + k0 + tx;
        g_Whi[o] = h;
        g_Wlo[o] = l;
    }
}

// ---------------------------------------------------------------------------
// HMMA GEMM mainloop (hardware-validated in R11/R13).
// ---------------------------------------------------------------------------
#define KITERS 32         // 1024 / 32
#define TILEB  10240      // 128 rows * 80 bytes
#define BUFSZ  40960      // 4 tiles (Ahi, Alo, Bhi, Blo)
#define ROWW   20         // words per smem row

__device__ __forceinline__ void hmma_gemm_tile(
    const __nv_bfloat16* __restrict__ Ah, const __nv_bfloat16* __restrict__ Al,
    const __nv_bfloat16* __restrict__ Bh, const __nv_bfloat16* __restrict__ Bl,
    char* smp, unsigned sbase, float acc[4][4][4])
{
    const int tid  = threadIdx.x;
    const int lane = tid & 31;
    const int wid  = tid >> 5;
    const int wm   = (wid & 1) * 64;
    const int wn   = (wid >> 1) * 32;
    const int fr   = lane >> 2;     // 0..7
    const int ft   = lane & 3;      // 0..3

    auto fill = [&](int buf, int k0) {
        const unsigned boff = sbase + buf * BUFSZ;
        #pragma unroll
        for (int it = 0; it < 8; ++it) {
            const int t = it >> 1;
            int e = tid + (it & 1) * 256;
            int r = e >> 2, c = e & 3;
            const __nv_bfloat16* gb = (t == 0) ? Ah : (t == 1) ? Al
                                     : (t == 2) ? Bh : Bl;
            cp_async16(boff + t * TILEB + r * 80 + c * 16,
                       gb + (size_t)r * Ev + k0 + c * 8);
        }
    };

    fill(0, 0); CP_COMMIT();

    for (int cIt = 0; cIt < KITERS; ++cIt) {
        const int buf = cIt & 1;
        if (cIt + 1 < KITERS) { fill(buf ^ 1, (cIt + 1) * 32); CP_COMMIT(); CP_WAIT(1); }
        else                  { CP_WAIT(0); }
        __syncthreads();

        const unsigned* A_h = (const unsigned*)(smp + buf * BUFSZ);
        const unsigned* A_l = (const unsigned*)(smp + buf * BUFSZ + TILEB);
        const unsigned* B_h = (const unsigned*)(smp + buf * BUFSZ + 2 * TILEB);
        const unsigned* B_l = (const unsigned*)(smp + buf * BUFSZ + 3 * TILEB);

        #pragma unroll
        for (int ks2 = 0; ks2 < 16; ks2 += 8) {
            unsigned bh[4][2], bl[4][2];
            #pragma unroll
            for (int na = 0; na < 4; ++na) {
                int base = (wn + na * 8 + fr) * ROWW + ks2 + ft;
                bh[na][0] = B_h[base];  bh[na][1] = B_h[base + 4];
                bl[na][0] = B_l[base];  bl[na][1] = B_l[base + 4];
            }
            #pragma unroll
            for (int ma = 0; ma < 4; ++ma) {
                int ab = (wm + ma * 16 + fr) * ROWW + ks2 + ft;
                unsigned ah[4], al[4];
                ah[0] = A_h[ab];            ah[1] = A_h[ab + 8 * ROWW];
                ah[2] = A_h[ab + 4];        ah[3] = A_h[ab + 8 * ROWW + 4];
                al[0] = A_l[ab];            al[1] = A_l[ab + 8 * ROWW];
                al[2] = A_l[ab + 4];        al[3] = A_l[ab + 8 * ROWW + 4];
                #pragma unroll
                for (int na = 0; na < 4; ++na) {
                    MMA_BF16(acc[ma][na], ah, bh[na]);
                    MMA_BF16(acc[ma][na], ah, bl[na]);
                    MMA_BF16(acc[ma][na], al, bh[na]);
                }
            }
        }
        __syncthreads();
    }
}

// ---------------------------------------------------------------------------
// QKV: X @ {Wq,Wk,Wv}. Epilogue writes bf16 hi/lo:
//   z=0 -> Q [B,H,S,D], z=1 -> K [B,H,S,D], z=2 -> V^T [B,H,D,S]
// grid (8, 256, 3)
// ---------------------------------------------------------------------------
__global__ __launch_bounds__(256, 2)
void qkv_mma()
{
    extern __shared__ char dsm[];
    unsigned raw   = smem_u32(dsm);
    unsigned sbase = (raw + 127) & ~127u;
    char* smp = dsm + (sbase - raw);

    const int z    = blockIdx.z;
    const int row0 = blockIdx.y * 128;
    const int col0 = blockIdx.x * 128;
    const size_t wz = (size_t)z * Ev * Ev;

    float acc[4][4][4] = {};
    hmma_gemm_tile(g_Xhi + (size_t)row0 * Ev, g_Xlo + (size_t)row0 * Ev,
                   g_Whi + wz + (size_t)col0 * Ev, g_Wlo + wz + (size_t)col0 * Ev,
                   smp, sbase, acc);

    const int lane = threadIdx.x & 31, wid = threadIdx.x >> 5;
    const int wm = (wid & 1) * 64, wn = (wid >> 1) * 32;
    const int grp = lane >> 2, tig = lane & 3;

    if (z < 2) {
        __nv_bfloat16* Ohi = (z == 0) ? g_Qhi : g_Khi;
        __nv_bfloat16* Olo = (z == 0) ? g_Qlo : g_Klo;
        #pragma unroll
        for (int ma = 0; ma < 4; ++ma) {
            #pragma unroll
            for (int na = 0; na < 4; ++na) {
                int n = col0 + wn + na * 8 + tig * 2;
                int h = n >> 6, d = n & 63;
                #pragma unroll
                for (int half = 0; half < 2; ++half) {
                    int m = row0 + wm + ma * 16 + grp + half * 8;
                    int b = m >> 9, s = m & 511;
                    size_t off = ((size_t)(b * Hv + h) * Sv + s) * Dv + d;
                    unsigned hw, lw;
                    split2(acc[ma][na][half*2], acc[ma][na][half*2+1], hw, lw);
                    *(unsigned*)(Ohi + off) = hw;
                    *(unsigned*)(Olo + off) = lw;
                }
            }
        }
    } else {
        #pragma unroll
        for (int ma = 0; ma < 4; ++ma) {
            #pragma unroll
            for (int na = 0; na < 4; ++na) {
                int n = col0 + wn + na * 8 + tig * 2;
                int h = n >> 6, d = n & 63;
                #pragma unroll
                for (int half = 0; half < 2; ++half) {
                    int m = row0 + wm + ma * 16 + grp + half * 8;
                    int b = m >> 9, s = m & 511;
                    #pragma unroll
                    for (int e = 0; e < 2; ++e) {
                        float x = acc[ma][na][half*2 + e];
                        __nv_bfloat16 hh = __float2bfloat16(x);
                        __nv_bfloat16 ll = __float2bfloat16(x - __bfloat162float(hh));
                        size_t off = ((size_t)(b * Hv + h) * Dv + d + e) * Sv + s;
                        g_Vthi[off] = hh;
                        g_Vtlo[off] = ll;
                    }
                }
            }
        }
    }
}

// ---------------------------------------------------------------------------
// Output projection: AO @ Wo + bo -> out.  grid (8, 256)
// ---------------------------------------------------------------------------
__global__ __launch_bounds__(256, 2)
void out_mma(const float* __restrict__ bo, float* __restrict__ Cout)
{
    extern __shared__ char dsm[];
    unsigned raw   = smem_u32(dsm);
    unsigned sbase = (raw + 127) & ~127u;
    char* smp = dsm + (sbase - raw);

    const int row0 = blockIdx.y * 128;
    const int col0 = blockIdx.x * 128;
    const size_t wz = (size_t)3 * Ev * Ev;

    float acc[4][4][4] = {};
    hmma_gemm_tile(g_AOhi + (size_t)row0 * Ev, g_AOlo + (size_t)row0 * Ev,
                   g_Whi + wz + (size_t)col0 * Ev, g_Wlo + wz + (size_t)col0 * Ev,
                   smp, sbase, acc);

    const int lane = threadIdx.x & 31, wid = threadIdx.x >> 5;
    const int wm = (wid & 1) * 64, wn = (wid >> 1) * 32;
    const int grp = lane >> 2, tig = lane & 3;

    #pragma unroll
    for (int ma = 0; ma < 4; ++ma) {
        #pragma unroll
        for (int na = 0; na < 4; ++na) {
            int n = col0 + wn + na * 8 + tig * 2;
            float2 bia = *(const float2*)(bo + n);
            #pragma unroll
            for (int half = 0; half < 2; ++half) {
                int m = row0 + wm + ma * 16 + grp + half * 8;
                float* dst = Cout + (size_t)m * Ev + n;
                *(float2*)dst = make_float2(acc[ma][na][half*2]   + bia.x,
                                            acc[ma][na][half*2+1] + bia.y);
            }
        }
    }
}

// ---------------------------------------------------------------------------
// Tensorized flash attention (causal, NO 1/sqrt(d) scale).
// Block: (b, h, 128-query tile). 8 warps x 16 rows. 64-key blocks,
// double-buffered cp.async (K hi/lo [key][d], V^T hi/lo [d][key]).
// 36-word padded smem rows -> conflict-free fragment LDS.
// S and P@V via 3-term bf16 mma.sync; softmax in registers (quad shfl).
// __launch_bounds__(256,2): cap regs at 128 so 2 CTAs/SM fit the RF.
// ---------------------------------------------------------------------------
#define TROW 36                 // words per smem row
#define TSZ  (64 * TROW * 4)    // 9216 B per tile
#define FBUF (4 * TSZ)          // 36864 B per buffer (Kh, Kl, Vth, Vtl)

__global__ __launch_bounds__(256, 2)
void flash_attn()
{
    extern __shared__ char dsm[];
    unsigned raw   = smem_u32(dsm);
    unsigned sbase = (raw + 127) & ~127u;
    char* smp = dsm + (sbase - raw);

    const int qt = blockIdx.x;          // 0..3 (128-row q tiles)
    const int h  = blockIdx.y;
    const int b  = blockIdx.z;
    const int q0 = qt * 128;

    const int tid  = threadIdx.x;
    const int lane = tid & 31;
    const int wid  = tid >> 5;
    const int grp  = lane >> 2;         // 0..7
    const int ft   = lane & 3;          // 0..3
    const int wm   = wid * 16;

    const long long bh = (long long)b * Hv + h;

    // Q fragments (persistent in registers): rows q0+wm .. +15, 32 words/row
    const unsigned* Qhw = (const unsigned*)g_Qhi + (bh * Sv + q0 + wm) * 32;
    const unsigned* Qlw = (const unsigned*)g_Qlo + (bh * Sv + q0 + wm) * 32;
    unsigned qh[4][4], ql[4][4];
    #pragma unroll
    for (int kc = 0; kc < 4; ++kc) {
        int w0 = grp * 32 + kc * 8 + ft;
        qh[kc][0] = Qhw[w0];       qh[kc][1] = Qhw[w0 + 256];
        qh[kc][2] = Qhw[w0 + 4];   qh[kc][3] = Qhw[w0 + 260];
        ql[kc][0] = Qlw[w0];       ql[kc][1] = Qlw[w0 + 256];
        ql[kc][2] = Qlw[w0 + 4];   ql[kc][3] = Qlw[w0 + 260];
    }

    const __nv_bfloat16* Kh  = g_Khi  + bh * Sv * Dv;
    const __nv_bfloat16* Kl  = g_Klo  + bh * Sv * Dv;
    const __nv_bfloat16* Vth = g_Vthi + bh * Dv * Sv;
    const __nv_bfloat16* Vtl = g_Vtlo + bh * Dv * Sv;

    float O[8][4] = {};
    float m0 = -1e30f, m1 = -1e30f, l0 = 0.f, l1 = 0.f;

    const int kbmax = 2 * (qt + 1);

    auto fill = [&](int buf, int kb) {
        const unsigned boff = sbase + buf * FBUF;
        #pragma unroll
        for (int it = 0; it < 8; ++it) {
            const int t = it >> 1;
            int e = tid + (it & 1) * 256;     // 0..511
            int r = e >> 3, c = e & 7;
            const __nv_bfloat16* g;
            if      (t == 0) g = Kh  + (size_t)(kb * 64 + r) * Dv + c * 8;
            else if (t == 1) g = Kl  + (size_t)(kb * 64 + r) * Dv + c * 8;
            else if (t == 2) g = Vth + (size_t)r * Sv + kb * 64 + c * 8;
            else             g = Vtl + (size_t)r * Sv + kb * 64 + c * 8;
            cp_async16(boff + t * TSZ + r * 144 + c * 16, g);
        }
    };

    fill(0, 0); CP_COMMIT();

    for (int kb = 0; kb < kbmax; ++kb) {
        const int buf = kb & 1;
        if (kb + 1 < kbmax) { fill(buf ^ 1, kb + 1); CP_COMMIT(); CP_WAIT(1); }
        else                { CP_WAIT(0); }
        __syncthreads();

        const unsigned* SK_h = (const unsigned*)(smp + buf * FBUF);
        const unsigned* SK_l = (const unsigned*)(smp + buf * FBUF + TSZ);
        const unsigned* SV_h = (const unsigned*)(smp + buf * FBUF + 2 * TSZ);
        const unsigned* SV_l = (const unsigned*)(smp + buf * FBUF + 3 * TSZ);

        // S = Q @ K^T (16x64 per warp), 3-term split
        float sacc[8][4] = {};
        #pragma unroll
        for (int kc = 0; kc < 4; ++kc) {
            unsigned bhf[8][2], blf[8][2];
            #pragma unroll
            for (int nt = 0; nt < 8; ++nt) {
                int w = (nt * 8 + grp) * TROW + kc * 8 + ft;
                bhf[nt][0] = SK_h[w];  bhf[nt][1] = SK_h[w + 4];
                blf[nt][0] = SK_l[w];  blf[nt][1] = SK_l[w + 4];
            }
            #pragma unroll
            for (int nt = 0; nt < 8; ++nt) {
                MMA_BF16(sacc[nt], qh[kc], bhf[nt]);
                MMA_BF16(sacc[nt], qh[kc], blf[nt]);
                MMA_BF16(sacc[nt], ql[kc], bhf[nt]);
            }
        }

        // causal mask (only the last two key blocks can cross the diagonal)
        if (kb >= kbmax - 2) {
            int r0 = q0 + wm + grp, r1 = r0 + 8;
            #pragma unroll
            for (int nt = 0; nt < 8; ++nt) {
                int c0 = kb * 64 + nt * 8 + 2 * ft;
                if (c0     > r0) sacc[nt][0] = -1e30f;
                if (c0 + 1 > r0) sacc[nt][1] = -1e30f;
                if (c0     > r1) sacc[nt][2] = -1e30f;
                if (c0 + 1 > r1) sacc[nt][3] = -1e30f;
            }
        }

        // online softmax in registers (rows grp / grp+8; quad holds full row)
        float mx0 = -1e30f, mx1 = -1e30f;
        #pragma unroll
        for (int nt = 0; nt < 8; ++nt) {
            mx0 = fmaxf(mx0, fmaxf(sacc[nt][0], sacc[nt][1]));
            mx1 = fmaxf(mx1, fmaxf(sacc[nt][2], sacc[nt][3]));
        }
        mx0 = fmaxf(mx0, __shfl_xor_sync(0xffffffffu, mx0, 1));
        mx0 = fmaxf(mx0, __shfl_xor_sync(0xffffffffu, mx0, 2));
        mx1 = fmaxf(mx1, __shfl_xor_sync(0xffffffffu, mx1, 1));
        mx1 = fmaxf(mx1, __shfl_xor_sync(0xffffffffu, mx1, 2));

        float mn0 = fmaxf(m0, mx0), mn1 = fmaxf(m1, mx1);
        float al0 = __expf(m0 - mn0), al1 = __expf(m1 - mn1);
        float ps0 = 0.f, ps1 = 0.f;
        #pragma unroll
        for (int nt = 0; nt < 8; ++nt) {
            sacc[nt][0] = __expf(sacc[nt][0] - mn0);
            sacc[nt][1] = __expf(sacc[nt][1] - mn0);
            sacc[nt][2] = __expf(sacc[nt][2] - mn1);
            sacc[nt][3] = __expf(sacc[nt][3] - mn1);
            ps0 += sacc[nt][0] + sacc[nt][1];
            ps1 += sacc[nt][2] + sacc[nt][3];
        }
        ps0 += __shfl_xor_sync(0xffffffffu, ps0, 1);
        ps0 += __shfl_xor_sync(0xffffffffu, ps0, 2);
        ps1 += __shfl_xor_sync(0xffffffffu, ps1, 1);
        ps1 += __shfl_xor_sync(0xffffffffu, ps1, 2);
        l0 = l0 * al0 + ps0;  l1 = l1 * al1 + ps1;
        m0 = mn0;             m1 = mn1;
        #pragma unroll
        for (int nt = 0; nt < 8; ++nt) {
            O[nt][0] *= al0;  O[nt][1] *= al0;
            O[nt][2] *= al1;  O[nt][3] *= al1;
        }

        // repack P (C layout -> A fragments, hi/lo split), lane-local
        unsigned ph[4][4], pl[4][4];
        #pragma unroll
        for (int kc = 0; kc < 4; ++kc) {
            split2(sacc[2*kc][0],   sacc[2*kc][1],   ph[kc][0], pl[kc][0]);
            split2(sacc[2*kc][2],   sacc[2*kc][3],   ph[kc][1], pl[kc][1]);
            split2(sacc[2*kc+1][0], sacc[2*kc+1][1], ph[kc][2], pl[kc][2]);
            split2(sacc[2*kc+1][2], sacc[2*kc+1][3], ph[kc][3], pl[kc][3]);
        }

        // O += P @ V  (V^T tile in smem is exactly B-fragment layout)
        #pragma unroll
        for (int kc = 0; kc < 4; ++kc) {
            unsigned vh[8][2], vl[8][2];
            #pragma unroll
            for (int nt = 0; nt < 8; ++nt) {
                int w = (nt * 8 + grp) * TROW + kc * 8 + ft;
                vh[nt][0] = SV_h[w];  vh[nt][1] = SV_h[w + 4];
                vl[nt][0] = SV_l[w];  vl[nt][1] = SV_l[w + 4];
            }
            #pragma unroll
            for (int nt = 0; nt < 8; ++nt) {
                MMA_BF16(O[nt], ph[kc], vh[nt]);
                MMA_BF16(O[nt], ph[kc], vl[nt]);
                MMA_BF16(O[nt], pl[kc], vh[nt]);
            }
        }
        __syncthreads();
    }

    // normalize + write AO hi/lo split into [B,S,E]
    float inv0 = 1.f / l0, inv1 = 1.f / l1;
    int r0 = q0 + wm + grp, r1 = r0 + 8;
    #pragma unroll
    for (int nt = 0; nt < 8; ++nt) {
        int d = nt * 8 + 2 * ft;
        size_t off0 = ((size_t)b * Sv + r0) * Ev + h * 64 + d;
        size_t off1 = ((size_t)b * Sv + r1) * Ev + h * 64 + d;
        unsigned hw, lw;
        split2(O[nt][0] * inv0, O[nt][1] * inv0, hw, lw);
        *(unsigned*)(g_AOhi + off0) = hw;
        *(unsigned*)(g_AOlo + off0) = lw;
        split2(O[nt][2] * inv1, O[nt][3] * inv1, hw, lw);
        *(unsigned*)(g_AOhi + off1) = hw;
        *(unsigned*)(g_AOlo + off1) = lw;
    }
}

// ---------------------------------------------------------------------------
extern "C" void kernel_launch(void* const* d_in, const int* in_sizes, int n_in,
                              void* d_out, int out_size)
{
    const float* X  = (const float*)d_in[0];
    const float* Wq = (const float*)d_in[1];
    const float* Wk = (const float*)d_in[2];
    const float* Wv = (const float*)d_in[3];
    const float* Wo = (const float*)d_in[4];
    const float* bo = (const float*)d_in[5];
    float* out = (float*)d_out;

    const int mma_smem   = 2 * BUFSZ + 128;       // 82048
    const int flash_smem = 2 * FBUF + 128;        // 73856
    cudaFuncSetAttribute(qkv_mma, cudaFuncAttributeMaxDynamicSharedMemorySize, mma_smem);
    cudaFuncSetAttribute(out_mma, cudaFuncAttributeMaxDynamicSharedMemorySize, mma_smem);
    cudaFuncSetAttribute(flash_attn, cudaFuncAttributeMaxDynamicSharedMemorySize, flash_smem);

    split_x<<<4096, 256>>>(X, Mtot * Ev);
    split_w<<<dim3(32, 32, 4), 256>>>(Wq, Wk, Wv, Wo);

    qkv_mma<<<dim3(8, 256, 3), 256, mma_smem>>>();

    flash_attn<<<dim3(4, Hv, Bv), 256, flash_smem>>>();

    out_mma<<<dim3(8, 256), 256, mma_smem>>>(bo, out);
}